// round 1
// baseline (speedup 1.0000x reference)
#include <cuda_runtime.h>
#include <cuda_bf16.h>
#include <math.h>

// Problem constants (fixed by the reference setup_inputs)
#define B 4
#define T 4096
#define C 64          // input dim == head size
#define HS 64
#define BT (B * T)    // 16384

// Scratch for q, k, v projections: 3 x 4 MB, device globals (no alloc allowed)
__device__ float g_q[BT * HS];
__device__ float g_k[BT * HS];
__device__ float g_v[BT * HS];

// ---------------------------------------------------------------------------
// Kernel 1: QKV projection.  out[t][h] = sum_c x[t][c] * W[h][c]
// Grid: (BT/64, 3). Block: 256 threads. Tile: 64 rows x 64 cols, 4x4/thread.
// ---------------------------------------------------------------------------
__global__ __launch_bounds__(256, 4)
void qkv_kernel(const float* __restrict__ x,
                const float* __restrict__ Wq,
                const float* __restrict__ Wk,
                const float* __restrict__ Wv)
{
    // padded to avoid bank conflicts: xs stride 67 (gcd(67,32)=1), ws stride 65
    __shared__ float xs[64 * 67];   // xs[c*67 + m] = x[row0+m][c]
    __shared__ float ws[64 * 65];   // ws[c*65 + h] = W[h][c]

    const float* W;
    float* out;
    if (blockIdx.y == 0)      { W = Wq; out = g_q; }
    else if (blockIdx.y == 1) { W = Wk; out = g_k; }
    else                      { W = Wv; out = g_v; }

    const int row0 = blockIdx.x * 64;
    const int tid = threadIdx.x;

    // Load W (64x64) transposed into smem
    #pragma unroll
    for (int idx = tid; idx < 64 * 64; idx += 256) {
        int h = idx >> 6;
        int c = idx & 63;
        ws[c * 65 + h] = W[idx];
    }
    // Load x tile (64 rows x 64 cols) transposed into smem
    #pragma unroll
    for (int idx = tid; idx < 64 * 64; idx += 256) {
        int m = idx >> 6;
        int c = idx & 63;
        xs[c * 67 + m] = x[(size_t)(row0 + m) * C + c];
    }
    __syncthreads();

    const int tm = (tid >> 4) * 4;   // row offset within tile
    const int tn = (tid & 15) * 4;   // col offset within tile

    float acc[4][4];
    #pragma unroll
    for (int i = 0; i < 4; i++)
        #pragma unroll
        for (int j = 0; j < 4; j++)
            acc[i][j] = 0.0f;

    #pragma unroll 8
    for (int c = 0; c < 64; ++c) {
        float a0 = xs[c * 67 + tm + 0];
        float a1 = xs[c * 67 + tm + 1];
        float a2 = xs[c * 67 + tm + 2];
        float a3 = xs[c * 67 + tm + 3];
        float b0 = ws[c * 65 + tn + 0];
        float b1 = ws[c * 65 + tn + 1];
        float b2 = ws[c * 65 + tn + 2];
        float b3 = ws[c * 65 + tn + 3];
        acc[0][0] += a0 * b0; acc[0][1] += a0 * b1; acc[0][2] += a0 * b2; acc[0][3] += a0 * b3;
        acc[1][0] += a1 * b0; acc[1][1] += a1 * b1; acc[1][2] += a1 * b2; acc[1][3] += a1 * b3;
        acc[2][0] += a2 * b0; acc[2][1] += a2 * b1; acc[2][2] += a2 * b2; acc[2][3] += a2 * b3;
        acc[3][0] += a3 * b0; acc[3][1] += a3 * b1; acc[3][2] += a3 * b2; acc[3][3] += a3 * b3;
    }

    #pragma unroll
    for (int i = 0; i < 4; i++) {
        float4 v4 = make_float4(acc[i][0], acc[i][1], acc[i][2], acc[i][3]);
        *reinterpret_cast<float4*>(&out[(size_t)(row0 + tm + i) * HS + tn]) = v4;
    }
}

// ---------------------------------------------------------------------------
// Kernel 2: windowed attention.  One warp per (b, t) row.
//   - 5 dot products q[t].k[s], s = t-2..t+2 (clamped), scale 1/8
//   - +1.0 bias for s > t (triu quirk of the reference), softmax over <=5 vals
//   - op row (64 fp32) and FULL attn row (4096 fp32: zeros + <=5 band weights)
// ---------------------------------------------------------------------------
__global__ __launch_bounds__(256, 8)
void attn_kernel(float* __restrict__ op_out,    // [B*T, 64]
                 float* __restrict__ attn_out)  // [B, T, T]
{
    const int warp_in_blk = threadIdx.x >> 5;
    const int lane = threadIdx.x & 31;
    const int w = blockIdx.x * 8 + warp_in_blk;   // global row id in [0, BT)
    const int b = w >> 12;        // / T
    const int t = w & (T - 1);    // % T

    // q fragment: 2 floats per lane
    const float2 myq = reinterpret_cast<const float2*>(g_q + (size_t)w * HS)[lane];

    // 5 banded dot products, warp-reduced
    float score[5];
    #pragma unroll
    for (int d = 0; d < 5; ++d) {
        const int s = t - 2 + d;
        const bool valid = (unsigned)s < (unsigned)T;
        float p = 0.0f;
        if (valid) {
            const float2 kk =
                reinterpret_cast<const float2*>(g_k + ((size_t)(b * T + s)) * HS)[lane];
            p = myq.x * kk.x + myq.y * kk.y;
        }
        #pragma unroll
        for (int off = 16; off > 0; off >>= 1)
            p += __shfl_xor_sync(0xFFFFFFFFu, p, off);
        // scale = C^-0.5 = 1/8 ; triu bias: +1.0 when s > t (d > 2)
        score[d] = valid ? (p * 0.125f + (d > 2 ? 1.0f : 0.0f)) : -1e30f;
    }

    // softmax over the (<=5) finite entries
    float m = score[0];
    #pragma unroll
    for (int d = 1; d < 5; ++d) m = fmaxf(m, score[d]);
    float p5[5];
    float sum = 0.0f;
    #pragma unroll
    for (int d = 0; d < 5; ++d) {
        p5[d] = expf(score[d] - m);
        sum += p5[d];
    }
    const float inv = 1.0f / sum;
    #pragma unroll
    for (int d = 0; d < 5; ++d) p5[d] *= inv;

    // op row: each lane owns 2 output channels
    float2 acc = make_float2(0.0f, 0.0f);
    #pragma unroll
    for (int d = 0; d < 5; ++d) {
        const int s = t - 2 + d;
        if ((unsigned)s < (unsigned)T) {
            const float2 vv =
                reinterpret_cast<const float2*>(g_v + ((size_t)(b * T + s)) * HS)[lane];
            acc.x += p5[d] * vv.x;
            acc.y += p5[d] * vv.y;
        }
    }
    reinterpret_cast<float2*>(op_out + (size_t)w * HS)[lane] = acc;

    // attn row: 4096 floats = 1024 float4; zeros except the band.
    const int lo = max(t - 2, 0);
    const int hi = min(t + 2, T - 1);
    const int fa = lo >> 2;
    const int fb = hi >> 2;       // fa or fa+1 (band of 5 spans <= 2 slots)

    // precompute the (<=2) nonzero float4 slots
    #define BV(s_) (((s_) >= lo && (s_) <= hi)                                   \
                      ? ((s_) == t - 2 ? p5[0]                                   \
                       : (s_) == t - 1 ? p5[1]                                   \
                       : (s_) == t     ? p5[2]                                   \
                       : (s_) == t + 1 ? p5[3] : p5[4])                          \
                      : 0.0f)
    const float4 va = make_float4(BV(4 * fa + 0), BV(4 * fa + 1),
                                  BV(4 * fa + 2), BV(4 * fa + 3));
    const float4 vb = make_float4(BV(4 * fb + 0), BV(4 * fb + 1),
                                  BV(4 * fb + 2), BV(4 * fb + 3));
    #undef BV

    float4* row4 = reinterpret_cast<float4*>(
        attn_out + (size_t)b * T * T + (size_t)t * T);

    #pragma unroll 4
    for (int i4 = lane; i4 < T / 4; i4 += 32) {
        float4 z = make_float4(0.0f, 0.0f, 0.0f, 0.0f);
        if (i4 == fa) z = va;
        if (i4 == fb) z = vb;
        row4[i4] = z;
    }
}

// ---------------------------------------------------------------------------
extern "C" void kernel_launch(void* const* d_in, const int* in_sizes, int n_in,
                              void* d_out, int out_size)
{
    const float* x  = (const float*)d_in[0];
    const float* Wq = (const float*)d_in[1];
    const float* Wk = (const float*)d_in[2];
    const float* Wv = (const float*)d_in[3];

    float* out = (float*)d_out;
    float* op_out   = out;                       // [B*T*HS]
    float* attn_out = out + (size_t)BT * HS;     // [B*T*T]

    dim3 g1(BT / 64, 3);
    qkv_kernel<<<g1, 256>>>(x, Wq, Wk, Wv);

    attn_kernel<<<BT / 8, 256>>>(op_out, attn_out);
}